// round 16
// baseline (speedup 1.0000x reference)
#include <cuda_runtime.h>
#include <cuda_fp16.h>
#include <cstdint>
#include <math.h>

#define NN 100000
#define DD 128
#define EE 250000
#define TT 3
#define ND (NN*DD)
#define ND4 (ND/4)
#define TNN (TT*NN)
#define NB_SCAN ((TNN + 255) / 256)
#define SCHUNK ((NB_SCAN + 255) / 256)

// -------- scratch --------
__device__ float  g_feat[ND];
__device__ __half g_feat16[ND];
__device__ __half g_t2h[ND];
__device__ __half g_skah[3*ND];
__device__ __half g_vh[3*ND];
__device__ __half g_w16[8][DD*DD];
__device__ __half g_wqa16[2][DD*DD];
__device__ __half g_wka16[2][DD*DD];
__device__ int    g_cntfill[2*TNN];      // [0:TNN) cnt, [TNN:2TNN) fill
__device__ int    g_offs[TNN];
__device__ int    g_partial[NB_SCAN];
__device__ int    g_ssrc[TT*EE];
__device__ float  g_inv[TNN];
__device__ float  g_gscale[NN];
__device__ float  g_colstats[2*DD];

// -------- setup kernels --------

__global__ void gather_feat_k(const float* __restrict__ n_emb, const int* __restrict__ ind,
                              float* __restrict__ feat, __half* __restrict__ feat16) {
    int idx = blockIdx.x * blockDim.x + threadIdx.x;
    if (idx >= ND4) return;
    int n = idx >> 5;
    float4 v = reinterpret_cast<const float4*>(n_emb)[(long)ind[n] * 32 + (idx & 31)];
    reinterpret_cast<float4*>(feat)[idx] = v;
    __half2* h = reinterpret_cast<__half2*>(feat16) + idx * 2;
    h[0] = __floats2half2_rn(v.x, v.y);
    h[1] = __floats2half2_rn(v.z, v.w);
}

__global__ void convert_wt8_k(const float* w0, const float* w1, const float* w2, const float* w3,
                              const float* w4, const float* w5, const float* w6, const float* w7,
                              __half* __restrict__ wt) {
    int i = blockIdx.x * blockDim.x + threadIdx.x;
    if (i >= 8*DD*DD) return;
    const float* ws[8] = {w0, w1, w2, w3, w4, w5, w6, w7};
    int m = i >> 14;
    int j = i & (DD*DD - 1);
    int n = j >> 7, k = j & 127;
    wt[(size_t)m * DD * DD + n * 128 + k] = __float2half(ws[m][k * 128 + n]);
}

__global__ void count_k(const int* __restrict__ dst, int* __restrict__ cnt) {
    int e = blockIdx.x * blockDim.x + threadIdx.x;
    if (e >= TT*EE) return;
    int t = e / EE;
    atomicAdd(&cnt[t * NN + dst[e]], 1);
}

__global__ void prep_k(const int* __restrict__ cnt, float* __restrict__ inv,
                       float* __restrict__ gscale) {
    int n = blockIdx.x * blockDim.x + threadIdx.x;
    if (n >= NN) return;
    int c0 = cnt[n], c1 = cnt[NN + n], c2 = cnt[2*NN + n];
    inv[n]        = 1.f / (float)max(c0, 1);
    inv[NN + n]   = 1.f / (float)max(c1, 1);
    inv[2*NN + n] = 1.f / (float)max(c2, 1);
    gscale[n] = (float)((c0 > 0) + (c1 > 0) + (c2 > 0));
}

__global__ void scan_block_k(const int* __restrict__ cnt, int* __restrict__ offs,
                             int* __restrict__ partial) {
    __shared__ int sh[256];
    int tid = threadIdx.x;
    int i = blockIdx.x * 256 + tid;
    int v = (i < TNN) ? cnt[i] : 0;
    sh[tid] = v; __syncthreads();
    #pragma unroll
    for (int off = 1; off < 256; off <<= 1) {
        int x = (tid >= off) ? sh[tid - off] : 0;
        __syncthreads();
        sh[tid] += x;
        __syncthreads();
    }
    if (i < TNN) offs[i] = sh[tid] - v;
    if (tid == 255) partial[blockIdx.x] = sh[tid];
}

__global__ void scan_partial_k(int* __restrict__ partial) {
    __shared__ int sh[256];
    int tid = threadIdx.x;
    int base = tid * SCHUNK;
    int loc[SCHUNK];
    int s = 0;
    #pragma unroll
    for (int j = 0; j < SCHUNK; j++) {
        int idx = base + j;
        int v = (idx < NB_SCAN) ? partial[idx] : 0;
        loc[j] = s; s += v;
    }
    sh[tid] = s; __syncthreads();
    #pragma unroll
    for (int off = 1; off < 256; off <<= 1) {
        int x = (tid >= off) ? sh[tid - off] : 0;
        __syncthreads();
        sh[tid] += x;
        __syncthreads();
    }
    int excl = sh[tid] - s;
    #pragma unroll
    for (int j = 0; j < SCHUNK; j++) {
        int idx = base + j;
        if (idx < NB_SCAN) partial[idx] = excl + loc[j];
    }
}

__global__ void scan_add_k(int* __restrict__ offs, const int* __restrict__ partial) {
    int i = blockIdx.x * 256 + threadIdx.x;
    if (i < TNN) offs[i] += partial[blockIdx.x];
}

__global__ void scatter_k(const int* __restrict__ src, const int* __restrict__ dst,
                          const int* __restrict__ offs, int* __restrict__ fill,
                          int* __restrict__ ssrc) {
    int e = blockIdx.x * blockDim.x + threadIdx.x;
    if (e >= TT*EE) return;
    int t = e / EE;
    int td = t * NN + dst[e];
    int pos = offs[td] + atomicAdd(&fill[td], 1);
    ssrc[pos] = src[e];
}

// -------- fp16 helpers --------

__device__ __forceinline__ void h4_to_f4(uint2 u, float4& f) {
    __half2 h0 = *reinterpret_cast<__half2*>(&u.x);
    __half2 h1 = *reinterpret_cast<__half2*>(&u.y);
    float2 a = __half22float2(h0), b = __half22float2(h1);
    f.x = a.x; f.y = a.y; f.z = b.x; f.w = b.y;
}

__device__ __forceinline__ uint2 f4_to_h4(float4 f) {
    __half2 h0 = __floats2half2_rn(f.x, f.y);
    __half2 h1 = __floats2half2_rn(f.z, f.w);
    uint2 u;
    u.x = *reinterpret_cast<uint32_t*>(&h0);
    u.y = *reinterpret_cast<uint32_t*>(&h1);
    return u;
}

// -------- common GEMM bits --------

#define G16_SMEM_BYTES ((size_t)2 * 128 * 136 * 2)

__device__ __forceinline__ void cp_async16(uint32_t saddr, const void* gptr, bool pred) {
    int sz = pred ? 16 : 0;
    asm volatile("cp.async.ca.shared.global [%0], [%1], 16, %2;"
                 :: "r"(saddr), "l"(gptr), "r"(sz));
}

__device__ __forceinline__ void mma_f16(float* c, const uint32_t* a, const uint32_t* b) {
    asm volatile("mma.sync.aligned.m16n8k16.row.col.f32.f16.f16.f32 "
                 "{%0,%1,%2,%3}, {%4,%5,%6,%7}, {%8,%9}, {%0,%1,%2,%3};"
                 : "+f"(c[0]), "+f"(c[1]), "+f"(c[2]), "+f"(c[3])
                 : "r"(a[0]), "r"(a[1]), "r"(a[2]), "r"(a[3]), "r"(b[0]), "r"(b[1]));
}

// -------- GCN GEMMs --------
// AEDGE 1 (gemm1): A-staging performs the GCN edge gather from feat16
//   (A param = feat16). EPI 0 store C; STATS 1 column stats.
// ABN 1 (gemm2): A-staging applies BN+ReLU; EPI 1 residual update.

template<int EPI, int STATS, int ABN, int AEDGE>
__global__ __launch_bounds__(256, 2) void gemm16(const __half* __restrict__ A,
                                                 const __half* __restrict__ Bt,
                                                 __half* __restrict__ C16, int M,
                                                 const float* __restrict__ bias,
                                                 float* __restrict__ featf,
                                                 __half* __restrict__ feat16,
                                                 const float* __restrict__ gamma,
                                                 const float* __restrict__ beta,
                                                 float* __restrict__ colstats,
                                                 const float* __restrict__ emb,
                                                 const int* __restrict__ ssrc,
                                                 const int* __restrict__ offs,
                                                 const int* __restrict__ cnt,
                                                 const float* __restrict__ inv,
                                                 const float* __restrict__ gscale) {
    extern __shared__ __half shh[];
    __half (*As)[136] = reinterpret_cast<__half(*)[136]>(shh);
    __half (*Bs)[136] = reinterpret_cast<__half(*)[136]>(shh + 128*136);
    __shared__ float bnm[128], bns[128], bnb[128];
    int tid = threadIdx.x;
    int lane = tid & 31, wid = tid >> 5;
    int wm = wid & 3, wn = wid >> 2;
    int g = lane >> 2, q = lane & 3;
    long m0 = (long)blockIdx.x * 128;

    if (ABN && tid < 128) {
        const float invN = 1.f / (float)NN;
        float mean = colstats[tid] * invN;
        float var  = colstats[128 + tid] * invN - mean * mean;
        bnm[tid] = mean;
        bns[tid] = rsqrtf(var + 1e-5f) * gamma[tid];
        bnb[tid] = beta[tid];
    }

    // B staging (always async)
    #pragma unroll
    for (int i = 0; i < 8; i++) {
        int v = tid + 256 * i;
        int r = v >> 4, kv = (v & 15) * 8;
        uint32_t sb = (uint32_t)__cvta_generic_to_shared(&Bs[r][kv]);
        cp_async16(sb, Bt + r * 128 + kv, true);
    }
    asm volatile("cp.async.commit_group;");

    if (AEDGE) {
        // GCN edge gather directly into As: warp-per-row, 16 rows/warp
        const uint2* f16 = reinterpret_cast<const uint2*>(A);
        #pragma unroll 1
        for (int rr = 0; rr < 16; rr++) {
            int r = wid * 16 + rr;
            long row = m0 + r;
            float4 acc4 = make_float4(0.f, 0.f, 0.f, 0.f);
            if (row < M) {
                float4 a; h4_to_f4(f16[row * 32 + lane], a);
                float gs = gscale[row];
                acc4 = make_float4(a.x * gs, a.y * gs, a.z * gs, a.w * gs);
                #pragma unroll
                for (int t = 0; t < TT; t++) {
                    int td = t * NN + (int)row;
                    int len = cnt[td];
                    if (len == 0) continue;
                    int beg = offs[td];
                    float4 s = make_float4(0.f, 0.f, 0.f, 0.f);
                    for (int i = 0; i < len; i++) {
                        int sn = ssrc[beg + i];
                        float4 f; h4_to_f4(f16[sn * 32 + lane], f);
                        s.x += f.x; s.y += f.y; s.z += f.z; s.w += f.w;
                    }
                    float4 e = reinterpret_cast<const float4*>(emb)[t * 32 + lane];
                    float w = inv[td];
                    acc4.x -= s.x * e.x * w; acc4.y -= s.y * e.y * w;
                    acc4.z -= s.z * e.z * w; acc4.w -= s.w * e.w * w;
                }
            }
            *reinterpret_cast<uint2*>(&As[r][lane * 4]) = f4_to_h4(acc4);
        }
        asm volatile("cp.async.wait_group 0;");
        __syncthreads();
    } else if (!ABN) {
        #pragma unroll
        for (int i = 0; i < 8; i++) {
            int v = tid + 256 * i;
            int r = v >> 4, kv = (v & 15) * 8;
            long row = m0 + r;
            uint32_t sa = (uint32_t)__cvta_generic_to_shared(&As[r][kv]);
            cp_async16(sa, A + row * 128 + kv, row < M);
        }
        asm volatile("cp.async.commit_group;");
        asm volatile("cp.async.wait_group 0;");
        __syncthreads();
    } else {
        #pragma unroll
        for (int batch = 0; batch < 2; batch++) {
            uint4 av[4];
            #pragma unroll
            for (int i = 0; i < 4; i++) {
                int v = tid + 256 * (batch * 4 + i);
                int r = v >> 4, kv = (v & 15) * 8;
                long row = m0 + r;
                av[i] = (row < M) ? *reinterpret_cast<const uint4*>(A + row * 128 + kv)
                                  : make_uint4(0u, 0u, 0u, 0u);
            }
            if (batch == 0) __syncthreads();
            #pragma unroll
            for (int i = 0; i < 4; i++) {
                int v = tid + 256 * (batch * 4 + i);
                int r = v >> 4, kv = (v & 15) * 8;
                uint32_t* u = &av[i].x;
                uint4 ov;
                uint32_t* o = &ov.x;
                #pragma unroll
                for (int j = 0; j < 4; j++) {
                    __half2 hv = *reinterpret_cast<__half2*>(&u[j]);
                    float2 f = __half22float2(hv);
                    int c0 = kv + 2*j;
                    f.x = fmaxf((f.x - bnm[c0])   * bns[c0]   + bnb[c0],   0.f);
                    f.y = fmaxf((f.y - bnm[c0+1]) * bns[c0+1] + bnb[c0+1], 0.f);
                    __half2 hr = __floats2half2_rn(f.x, f.y);
                    o[j] = *reinterpret_cast<uint32_t*>(&hr);
                }
                *reinterpret_cast<uint4*>(&As[r][kv]) = ov;
            }
        }
        asm volatile("cp.async.wait_group 0;");
        __syncthreads();
    }

    float acc[2][8][4];
    #pragma unroll
    for (int mt = 0; mt < 2; mt++)
        #pragma unroll
        for (int nt = 0; nt < 8; nt++)
            #pragma unroll
            for (int i = 0; i < 4; i++) acc[mt][nt][i] = 0.f;

    #pragma unroll
    for (int ks = 0; ks < 8; ks++) {
        int kk = ks * 16;
        uint32_t a[2][4], b[8][2];
        #pragma unroll
        for (int mt = 0; mt < 2; mt++) {
            int row = wm * 32 + mt * 16 + g;
            a[mt][0] = *reinterpret_cast<const uint32_t*>(&As[row][kk + 2*q]);
            a[mt][1] = *reinterpret_cast<const uint32_t*>(&As[row + 8][kk + 2*q]);
            a[mt][2] = *reinterpret_cast<const uint32_t*>(&As[row][kk + 2*q + 8]);
            a[mt][3] = *reinterpret_cast<const uint32_t*>(&As[row + 8][kk + 2*q + 8]);
        }
        #pragma unroll
        for (int nt = 0; nt < 8; nt++) {
            int col = wn * 64 + nt * 8 + g;
            b[nt][0] = *reinterpret_cast<const uint32_t*>(&Bs[col][kk + 2*q]);
            b[nt][1] = *reinterpret_cast<const uint32_t*>(&Bs[col][kk + 2*q + 8]);
        }
        #pragma unroll
        for (int mt = 0; mt < 2; mt++)
            #pragma unroll
            for (int nt = 0; nt < 8; nt++)
                mma_f16(acc[mt][nt], a[mt], b[nt]);
    }

    #pragma unroll
    for (int mt = 0; mt < 2; mt++) {
        #pragma unroll
        for (int h = 0; h < 2; h++) {
            long row = m0 + wm * 32 + mt * 16 + g + h * 8;
            if (row >= M) continue;
            #pragma unroll
            for (int nt = 0; nt < 8; nt++) {
                int col = wn * 64 + nt * 8 + q * 2;
                long base = row * 128 + col;
                float v0 = acc[mt][nt][h * 2], v1 = acc[mt][nt][h * 2 + 1];
                if (EPI == 0) {
                    *reinterpret_cast<__half2*>(&C16[base]) = __floats2half2_rn(v0, v1);
                } else {
                    float2 prev = *reinterpret_cast<const float2*>(&featf[base]);
                    float n0 = prev.x + v0 + bias[col];
                    float n1 = prev.y + v1 + bias[col + 1];
                    *reinterpret_cast<float2*>(&featf[base]) = make_float2(n0, n1);
                    *reinterpret_cast<__half2*>(&feat16[base]) = __floats2half2_rn(n0, n1);
                }
            }
        }
    }

    if (STATS) {
        #pragma unroll
        for (int nt = 0; nt < 8; nt++) {
            float s0 = 0.f, q0 = 0.f, s1 = 0.f, q1 = 0.f;
            #pragma unroll
            for (int mt = 0; mt < 2; mt++)
                #pragma unroll
                for (int h = 0; h < 2; h++) {
                    float v0 = acc[mt][nt][h*2], v1 = acc[mt][nt][h*2+1];
                    s0 += v0; q0 += v0*v0; s1 += v1; q1 += v1*v1;
                }
            #pragma unroll
            for (int off = 4; off < 32; off <<= 1) {
                s0 += __shfl_xor_sync(0xffffffffu, s0, off);
                q0 += __shfl_xor_sync(0xffffffffu, q0, off);
                s1 += __shfl_xor_sync(0xffffffffu, s1, off);
                q1 += __shfl_xor_sync(0xffffffffu, q1, off);
            }
            if (g == 0) {
                int col = wn * 64 + nt * 8 + q * 2;
                atomicAdd(&colstats[col], s0);
                atomicAdd(&colstats[128 + col], q0);
                atomicAdd(&colstats[col + 1], s1);
                atomicAdd(&colstats[128 + col + 1], q1);
            }
        }
    }
}

// -------- fused attention output (unchanged from R15) --------

template<int FIN>
__global__ __launch_bounds__(256, 2) void gemm_attn_out(
    const __half* __restrict__ A, const __half* __restrict__ Bq,
    const __half* __restrict__ Bp, int M,
    const float* __restrict__ bias, float* __restrict__ featf,
    __half* __restrict__ feat16, const __half* __restrict__ ska,
    const __half* __restrict__ vv, float* __restrict__ fout) {
    extern __shared__ __half shh[];
    __half (*As)[136] = reinterpret_cast<__half(*)[136]>(shh);
    __half (*Bs)[136] = reinterpret_cast<__half(*)[136]>(shh + 128*136);
    int tid = threadIdx.x;
    int lane = tid & 31, wid = tid >> 5;
    int wm = wid & 3, wn = wid >> 2;
    int g = lane >> 2, q = lane & 3;
    long m0 = (long)blockIdx.x * 128;

    #pragma unroll
    for (int i = 0; i < 8; i++) {
        int v = tid + 256 * i;
        int r = v >> 4, kv = (v & 15) * 8;
        long row = m0 + r;
        uint32_t sa = (uint32_t)__cvta_generic_to_shared(&As[r][kv]);
        cp_async16(sa, A + row * 128 + kv, row < M);
        uint32_t sb = (uint32_t)__cvta_generic_to_shared(&Bs[r][kv]);
        cp_async16(sb, Bq + r * 128 + kv, true);
    }
    asm volatile("cp.async.commit_group;");
    asm volatile("cp.async.wait_group 0;");
    __syncthreads();

    float acc[2][8][4];
    #pragma unroll
    for (int mt = 0; mt < 2; mt++)
        #pragma unroll
        for (int nt = 0; nt < 8; nt++)
            #pragma unroll
            for (int i = 0; i < 4; i++) acc[mt][nt][i] = 0.f;

    #pragma unroll
    for (int ks = 0; ks < 8; ks++) {
        int kk = ks * 16;
        uint32_t a[2][4], b[8][2];
        #pragma unroll
        for (int mt = 0; mt < 2; mt++) {
            int row = wm * 32 + mt * 16 + g;
            a[mt][0] = *reinterpret_cast<const uint32_t*>(&As[row][kk + 2*q]);
            a[mt][1] = *reinterpret_cast<const uint32_t*>(&As[row + 8][kk + 2*q]);
            a[mt][2] = *reinterpret_cast<const uint32_t*>(&As[row][kk + 2*q + 8]);
            a[mt][3] = *reinterpret_cast<const uint32_t*>(&As[row + 8][kk + 2*q + 8]);
        }
        #pragma unroll
        for (int nt = 0; nt < 8; nt++) {
            int col = wn * 64 + nt * 8 + g;
            b[nt][0] = *reinterpret_cast<const uint32_t*>(&Bs[col][kk + 2*q]);
            b[nt][1] = *reinterpret_cast<const uint32_t*>(&Bs[col][kk + 2*q + 8]);
        }
        #pragma unroll
        for (int mt = 0; mt < 2; mt++)
            #pragma unroll
            for (int nt = 0; nt < 8; nt++)
                mma_f16(acc[mt][nt], a[mt], b[nt]);
    }
    __syncthreads();

    #pragma unroll
    for (int i = 0; i < 8; i++) {
        int v = tid + 256 * i;
        int r = v >> 4, kv = (v & 15) * 8;
        uint32_t sb = (uint32_t)__cvta_generic_to_shared(&Bs[r][kv]);
        cp_async16(sb, Bp + r * 128 + kv, true);
    }
    asm volatile("cp.async.commit_group;");

    #pragma unroll
    for (int mt = 0; mt < 2; mt++) {
        #pragma unroll
        for (int h = 0; h < 2; h++) {
            int rloc = wm * 32 + mt * 16 + g + h * 8;
            long row = m0 + rloc;
            bool ok = row < M;
            #pragma unroll
            for (int nt = 0; nt < 8; nt++) {
                int col = wn * 64 + nt * 8 + q * 2;
                long base = row * 128 + col;
                float o0 = 0.f, o1 = 0.f;
                if (ok) {
                    float v0 = acc[mt][nt][h * 2], v1 = acc[mt][nt][h * 2 + 1];
                    float2 s0 = __half22float2(*reinterpret_cast<const __half2*>(ska + base));
                    float2 s1 = __half22float2(*reinterpret_cast<const __half2*>(ska + base + (long)ND));
                    float2 s2 = __half22float2(*reinterpret_cast<const __half2*>(ska + base + 2L*ND));
                    float2 w0 = __half22float2(*reinterpret_cast<const __half2*>(vv + base));
                    float2 w1 = __half22float2(*reinterpret_cast<const __half2*>(vv + base + (long)ND));
                    float2 w2 = __half22float2(*reinterpret_cast<const __half2*>(vv + base + 2L*ND));
                    {
                        float l0 = v0 - s0.x, l1 = v0 - s1.x, l2 = v0 - s2.x;
                        float mx = fmaxf(l0, fmaxf(l1, l2));
                        float e0 = __expf(l0-mx), e1 = __expf(l1-mx), e2 = __expf(l2-mx);
                        o0 = (e0*w0.x + e1*w1.x + e2*w2.x) / (e0 + e1 + e2);
                    }
                    {
                        float l0 = v1 - s0.y, l1 = v1 - s1.y, l2 = v1 - s2.y;
                        float mx = fmaxf(l0, fmaxf(l1, l2));
                        float e0 = __expf(l0-mx), e1 = __expf(l1-mx), e2 = __expf(l2-mx);
                        o1 = (e0*w0.y + e1*w1.y + e2*w2.y) / (e0 + e1 + e2);
                    }
                }
                *reinterpret_cast<__half2*>(&As[rloc][col]) = __floats2half2_rn(o0, o1);
            }
        }
    }
    asm volatile("cp.async.wait_group 0;");
    __syncthreads();

    #pragma unroll
    for (int mt = 0; mt < 2; mt++)
        #pragma unroll
        for (int nt = 0; nt < 8; nt++)
            #pragma unroll
            for (int i = 0; i < 4; i++) acc[mt][nt][i] = 0.f;

    #pragma unroll
    for (int ks = 0; ks < 8; ks++) {
        int kk = ks * 16;
        uint32_t a[2][4], b[8][2];
        #pragma unroll
        for (int mt = 0; mt < 2; mt++) {
            int row = wm * 32 + mt * 16 + g;
            a[mt][0] = *reinterpret_cast<const uint32_t*>(&As[row][kk + 2*q]);
            a[mt][1] = *reinterpret_cast<const uint32_t*>(&As[row + 8][kk + 2*q]);
            a[mt][2] = *reinterpret_cast<const uint32_t*>(&As[row][kk + 2*q + 8]);
            a[mt][3] = *reinterpret_cast<const uint32_t*>(&As[row + 8][kk + 2*q + 8]);
        }
        #pragma unroll
        for (int nt = 0; nt < 8; nt++) {
            int col = wn * 64 + nt * 8 + g;
            b[nt][0] = *reinterpret_cast<const uint32_t*>(&Bs[col][kk + 2*q]);
            b[nt][1] = *reinterpret_cast<const uint32_t*>(&Bs[col][kk + 2*q + 8]);
        }
        #pragma unroll
        for (int mt = 0; mt < 2; mt++)
            #pragma unroll
            for (int nt = 0; nt < 8; nt++)
                mma_f16(acc[mt][nt], a[mt], b[nt]);
    }

    #pragma unroll
    for (int mt = 0; mt < 2; mt++) {
        #pragma unroll
        for (int h = 0; h < 2; h++) {
            long row = m0 + wm * 32 + mt * 16 + g + h * 8;
            if (row >= M) continue;
            #pragma unroll
            for (int nt = 0; nt < 8; nt++) {
                int col = wn * 64 + nt * 8 + q * 2;
                long base = row * 128 + col;
                float v0 = acc[mt][nt][h * 2], v1 = acc[mt][nt][h * 2 + 1];
                float2 prev = *reinterpret_cast<const float2*>(&featf[base]);
                float n0 = prev.x + v0 + bias[col];
                float n1 = prev.y + v1 + bias[col + 1];
                if (FIN == 0) {
                    *reinterpret_cast<float2*>(&featf[base]) = make_float2(n0, n1);
                    *reinterpret_cast<__half2*>(&feat16[base]) = __floats2half2_rn(n0, n1);
                } else {
                    *reinterpret_cast<float2*>(&fout[base]) = make_float2(n0, n1);
                }
            }
        }
    }
}

// -------- seq2 with fused attn edge gather: A rows = key rows computed on the fly --------
#define SEQ_SMEM_BYTES ((size_t)3 * 128 * 136 * 2)

__global__ __launch_bounds__(256, 2) void gemm_seq2e(const __half* __restrict__ feat16,
                                                     const __half* __restrict__ B1t,
                                                     const __half* __restrict__ B2t,
                                                     __half* __restrict__ C1,
                                                     __half* __restrict__ C2, int M,
                                                     const float* __restrict__ emb,
                                                     const int* __restrict__ ssrc,
                                                     const int* __restrict__ offs,
                                                     const int* __restrict__ cnt,
                                                     const float* __restrict__ inv) {
    extern __shared__ __half sh[];
    __half (*As)[136]  = reinterpret_cast<__half(*)[136]>(sh);
    __half (*Bs1)[136] = reinterpret_cast<__half(*)[136]>(sh + 128*136);
    __half (*Bs2)[136] = reinterpret_cast<__half(*)[136]>(sh + 2*128*136);
    int tid = threadIdx.x;
    int lane = tid & 31, wid = tid >> 5;
    int wm = wid & 3, wn = wid >> 2;
    int g = lane >> 2, q = lane & 3;
    long m0 = (long)blockIdx.x * 128;

    #pragma unroll
    for (int i = 0; i < 8; i++) {
        int v = tid + 256 * i;
        int r = v >> 4, kv = (v & 15) * 8;
        uint32_t s1 = (uint32_t)__cvta_generic_to_shared(&Bs1[r][kv]);
        cp_async16(s1, B1t + r * 128 + kv, true);
        uint32_t s2 = (uint32_t)__cvta_generic_to_shared(&Bs2[r][kv]);
        cp_async16(s2, B2t + r * 128 + kv, true);
    }
    asm volatile("cp.async.commit_group;");

    // attn edge gather into As: warp-per-row, 16 rows/warp
    const uint2* f16 = reinterpret_cast<const uint2*>(feat16);
    #pragma unroll 1
    for (int rr = 0; rr < 16; rr++) {
        int r = wid * 16 + rr;
        long gw = m0 + r;
        float4 out = make_float4(0.f, 0.f, 0.f, 0.f);
        if (gw < M) {
            int len = cnt[gw];
            int beg = offs[gw];
            float4 s = make_float4(0.f, 0.f, 0.f, 0.f);
            for (int i = 0; i < len; i++) {
                int sn = ssrc[beg + i];
                float4 f; h4_to_f4(f16[sn * 32 + lane], f);
                s.x += f.x; s.y += f.y; s.z += f.z; s.w += f.w;
            }
            int t = (int)(gw / NN);
            float4 e = reinterpret_cast<const float4*>(emb)[t * 32 + lane];
            float w = inv[gw];
            out = make_float4(s.x*e.x*w, s.y*e.y*w, s.z*e.z*w, s.w*e.w*w);
        }
        *reinterpret_cast<uint2*>(&As[r][lane * 4]) = f4_to_h4(out);
    }
    asm volatile("cp.async.wait_group 0;");
    __syncthreads();

    #pragma unroll
    for (int pass = 0; pass < 2; pass++) {
        __half (*Bs)[136] = pass ? Bs2 : Bs1;
        __half* C = pass ? C2 : C1;
        float acc[2][8][4];
        #pragma unroll
        for (int mt = 0; mt < 2; mt++)
            #pragma unroll
            for (int nt = 0; nt < 8; nt++)
                #pragma unroll
                for (int i = 0; i < 4; i++) acc[mt][nt][i] = 0.f;

        #pragma unroll
        for (int ks = 0; ks < 8; ks++) {
            int kk = ks * 16;
            uint32_t a[2][4], b[8][2];
            #pragma unroll
            for (int mt = 0; mt < 2; mt++) {
                int row = wm * 32 + mt * 16 + g;
                a[mt][0] = *reinterpret_cast<const uint32_t*>(&As[row][kk + 2*q]);
                a[mt][1] = *reinterpret_cast<const uint32_t*>(&As[row + 8][kk + 2*q]);
                a[mt][2] = *reinterpret_cast<const uint32_t*>(&As[row][kk + 2*q + 8]);
                a[mt][3] = *reinterpret_cast<const uint32_t*>(&As[row + 8][kk + 2*q + 8]);
            }
            #pragma unroll
            for (int nt = 0; nt < 8; nt++) {
                int col = wn * 64 + nt * 8 + g;
                b[nt][0] = *reinterpret_cast<const uint32_t*>(&Bs[col][kk + 2*q]);
                b[nt][1] = *reinterpret_cast<const uint32_t*>(&Bs[col][kk + 2*q + 8]);
            }
            #pragma unroll
            for (int mt = 0; mt < 2; mt++)
                #pragma unroll
                for (int nt = 0; nt < 8; nt++)
                    mma_f16(acc[mt][nt], a[mt], b[nt]);
        }

        #pragma unroll
        for (int mt = 0; mt < 2; mt++)
            #pragma unroll
            for (int h = 0; h < 2; h++) {
                long row = m0 + wm * 32 + mt * 16 + g + h * 8;
                if (row >= M) continue;
                #pragma unroll
                for (int nt = 0; nt < 8; nt++) {
                    int col = wn * 64 + nt * 8 + q * 2;
                    *reinterpret_cast<__half2*>(&C[row * 128 + col]) =
                        __floats2half2_rn(acc[mt][nt][h*2], acc[mt][nt][h*2+1]);
                }
            }
    }
}

// -------- merged tf32 mini-GEMMs --------

#define GSTAGE_A (128*36)
#define GSTAGE_B (32*136)
#define GSTAGE   (GSTAGE_A + GSTAGE_B)
#define GEMM_SMEM_BYTES (2*GSTAGE*4)

struct W4Args {
    const float* A[4];
    const float* B[4];
    __half* C[4];
};

__device__ __forceinline__ void mma_tf32(float* c, const uint32_t* a, const uint32_t* b) {
    asm volatile("mma.sync.aligned.m16n8k8.row.col.f32.tf32.tf32.f32 "
                 "{%0,%1,%2,%3}, {%4,%5,%6,%7}, {%8,%9}, {%0,%1,%2,%3};"
                 : "+f"(c[0]), "+f"(c[1]), "+f"(c[2]), "+f"(c[3])
                 : "r"(a[0]), "r"(a[1]), "r"(a[2]), "r"(a[3]), "r"(b[0]), "r"(b[1]));
}

__global__ __launch_bounds__(256) void gemm_w_tr4(W4Args args) {
    const float* A = args.A[blockIdx.x];
    const float* B = args.B[blockIdx.x];
    __half* C16t = args.C[blockIdx.x];
    extern __shared__ float smf[];
    int tid = threadIdx.x;
    int lane = tid & 31, wid = tid >> 5;
    int wm = wid & 3, wn = wid >> 2;
    int g = lane >> 2, q = lane & 3;

    float acc[2][8][4];
    #pragma unroll
    for (int mt = 0; mt < 2; mt++)
        #pragma unroll
        for (int nt = 0; nt < 8; nt++)
            #pragma unroll
            for (int i = 0; i < 4; i++) acc[mt][nt][i] = 0.f;

    int ar[4], ac_[4], br[4], bc[4];
    #pragma unroll
    for (int i = 0; i < 4; i++) {
        int idx = (tid + 256 * i) * 4;
        ar[i] = idx >> 5; ac_[i] = idx & 31;
        br[i] = idx >> 7; bc[i] = idx & 127;
    }

    auto prefetch = [&](int kc, int s) {
        float* As = smf + s * GSTAGE;
        float* Bs = As + GSTAGE_A;
        #pragma unroll
        for (int i = 0; i < 4; i++) {
            uint32_t sa = (uint32_t)__cvta_generic_to_shared(&As[ar[i]*36 + ac_[i]]);
            cp_async16(sa, A + ar[i] * 128 + kc * 32 + ac_[i], true);
        }
        #pragma unroll
        for (int i = 0; i < 4; i++) {
            uint32_t sb = (uint32_t)__cvta_generic_to_shared(&Bs[br[i]*136 + bc[i]]);
            cp_async16(sb, B + (kc * 32 + br[i]) * 128 + bc[i], true);
        }
        asm volatile("cp.async.commit_group;");
    };

    prefetch(0, 0);
    for (int kc = 0; kc < 4; kc++) {
        if (kc < 3) {
            prefetch(kc + 1, (kc + 1) & 1);
            asm volatile("cp.async.wait_group 1;");
        } else {
            asm volatile("cp.async.wait_group 0;");
        }
        __syncthreads();
        const uint32_t* As = reinterpret_cast<const uint32_t*>(smf + (kc & 1) * GSTAGE);
        const uint32_t* Bs = As + GSTAGE_A;
        #pragma unroll
        for (int ks = 0; ks < 4; ks++) {
            int kc8 = ks * 8;
            uint32_t a[2][4], b[8][2];
            #pragma unroll
            for (int mt = 0; mt < 2; mt++) {
                int row = wm * 32 + mt * 16 + g;
                a[mt][0] = As[row*36 + kc8 + q];
                a[mt][1] = As[(row+8)*36 + kc8 + q];
                a[mt][2] = As[row*36 + kc8 + q + 4];
                a[mt][3] = As[(row+8)*36 + kc8 + q + 4];
            }
            #pragma unroll
            for (int nt = 0; nt < 8; nt++) {
                int col = wn * 64 + nt * 8 + g;
                b[nt][0] = Bs[(kc8 + q)*136 + col];
                b[nt][1] = Bs[(kc8 + q + 4)*136 + col];
            }
            #pragma unroll
            for (int mt = 0; mt < 2; mt++)
                #pragma unroll
                for (int nt = 0; nt < 8; nt++)
                    mma_tf32(acc[mt][nt], a[mt], b[nt]);
        }
        __syncthreads();
    }

    #pragma unroll
    for (int mt = 0; mt < 2; mt++) {
        #pragma unroll
        for (int h = 0; h < 2; h++) {
            int row = wm * 32 + mt * 16 + g + h * 8;
            #pragma unroll
            for (int nt = 0; nt < 8; nt++) {
                int col = wn * 64 + nt * 8 + q * 2;
                C16t[(long)col * 128 + row]       = __float2half(acc[mt][nt][h*2]);
                C16t[(long)(col + 1) * 128 + row] = __float2half(acc[mt][nt][h*2+1]);
            }
        }
    }
}

// -------- host --------

extern "C" void kernel_launch(void* const* d_in, const int* in_sizes, int n_in,
                              void* d_out, int out_size) {
    const float* e_emb = (const float*)d_in[1];
    const int* node_ind = (const int*)d_in[26];
    const int* edge_src = (const int*)d_in[27];
    const int* edge_dst = (const int*)d_in[28];

    float *feat, *inv, *gscale, *colstats;
    __half *feat16, *t2h, *skah, *vh, *w16, *wqa16, *wka16;
    int *cntfill, *offs, *partial, *ssrc;
    cudaGetSymbolAddress((void**)&feat, g_feat);
    cudaGetSymbolAddress((void**)&feat16, g_feat16);
    cudaGetSymbolAddress((void**)&t2h, g_t2h);
    cudaGetSymbolAddress((void**)&skah, g_skah);
    cudaGetSymbolAddress((void**)&vh, g_vh);
    cudaGetSymbolAddress((void**)&w16, g_w16);
    cudaGetSymbolAddress((void**)&wqa16, g_wqa16);
    cudaGetSymbolAddress((void**)&wka16, g_wka16);
    cudaGetSymbolAddress((void**)&cntfill, g_cntfill);
    cudaGetSymbolAddress((void**)&offs, g_offs);
    cudaGetSymbolAddress((void**)&partial, g_partial);
    cudaGetSymbolAddress((void**)&ssrc, g_ssrc);
    cudaGetSymbolAddress((void**)&inv, g_inv);
    cudaGetSymbolAddress((void**)&gscale, g_gscale);
    cudaGetSymbolAddress((void**)&colstats, g_colstats);
    int* cnt = cntfill;
    int* fill = cntfill + TNN;

    cudaFuncSetAttribute(gemm_w_tr4, cudaFuncAttributeMaxDynamicSharedMemorySize, GEMM_SMEM_BYTES);
    cudaFuncSetAttribute(gemm_seq2e, cudaFuncAttributeMaxDynamicSharedMemorySize, (int)SEQ_SMEM_BYTES);
    cudaFuncSetAttribute((const void*)gemm16<0,1,0,1>, cudaFuncAttributeMaxDynamicSharedMemorySize, (int)G16_SMEM_BYTES);
    cudaFuncSetAttribute((const void*)gemm16<1,0,1,0>, cudaFuncAttributeMaxDynamicSharedMemorySize, (int)G16_SMEM_BYTES);
    cudaFuncSetAttribute((const void*)gemm_attn_out<0>, cudaFuncAttributeMaxDynamicSharedMemorySize, (int)G16_SMEM_BYTES);
    cudaFuncSetAttribute((const void*)gemm_attn_out<1>, cudaFuncAttributeMaxDynamicSharedMemorySize, (int)G16_SMEM_BYTES);

    const int TPB = 256;
    const int ND4_BLK = (ND4 + TPB - 1) / TPB;
    const int E_BLK = (TT*EE + TPB - 1) / TPB;
    const int G1 = (NN + 127) / 128;
    const int G3 = (TNN + 127) / 128;

    convert_wt8_k<<<(8*DD*DD + TPB - 1)/TPB, TPB>>>(
        (const float*)d_in[2],  (const float*)d_in[5],  (const float*)d_in[9],  (const float*)d_in[12],
        (const float*)d_in[14], (const float*)d_in[17], (const float*)d_in[21], (const float*)d_in[24],
        w16);

    W4Args wargs;
    wargs.A[0] = (const float*)d_in[7];  wargs.B[0] = (const float*)d_in[10]; wargs.C[0] = wqa16;
    wargs.A[1] = (const float*)d_in[8];  wargs.B[1] = (const float*)d_in[10]; wargs.C[1] = wka16;
    wargs.A[2] = (const float*)d_in[19]; wargs.B[2] = (const float*)d_in[22]; wargs.C[2] = wqa16 + DD*DD;
    wargs.A[3] = (const float*)d_in[20]; wargs.B[3] = (const float*)d_in[22]; wargs.C[3] = wka16 + DD*DD;
    gemm_w_tr4<<<4, 256, GEMM_SMEM_BYTES>>>(wargs);

    cudaMemsetAsync(cntfill, 0, 2*TNN*sizeof(int), 0);
    count_k<<<E_BLK, TPB>>>(edge_dst, cnt);
    prep_k<<<(NN + TPB - 1)/TPB, TPB>>>(cnt, inv, gscale);
    scan_block_k<<<NB_SCAN, 256>>>(cnt, offs, partial);
    scan_partial_k<<<1, 256>>>(partial);
    scan_add_k<<<NB_SCAN, 256>>>(offs, partial);
    scatter_k<<<E_BLK, TPB>>>(edge_src, edge_dst, offs, fill, ssrc);
    gather_feat_k<<<ND4_BLK, TPB>>>((const float*)d_in[0], node_ind, feat, feat16);

    const float* gcn_gamma[2] = {(const float*)d_in[3],  (const float*)d_in[15]};
    const float* gcn_beta[2]  = {(const float*)d_in[4],  (const float*)d_in[16]};
    const float* gcn_b2[2]    = {(const float*)d_in[6],  (const float*)d_in[18]};
    const float* at_bp[2]     = {(const float*)d_in[13], (const float*)d_in[25]};

    for (int L = 0; L < 2; L++) {
        const __half* w1t = w16 + (size_t)(L*4 + 0) * DD * DD;
        const __half* w2t = w16 + (size_t)(L*4 + 1) * DD * DD;
        const __half* wvt = w16 + (size_t)(L*4 + 2) * DD * DD;
        const __half* wpt = w16 + (size_t)(L*4 + 3) * DD * DD;
        const __half* wqaL = wqa16 + (size_t)L * DD * DD;
        const __half* wkaL = wka16 + (size_t)L * DD * DD;

        // ---- GCN layer: gemm1 fuses the edge gather; gemm2 fuses BN+ReLU ----
        cudaMemsetAsync(colstats, 0, 2*DD*sizeof(float), 0);
        gemm16<0,1,0,1><<<G1, 256, G16_SMEM_BYTES>>>(feat16, w1t, t2h, NN, nullptr, nullptr, nullptr,
                                                     nullptr, nullptr, colstats,
                                                     e_emb, ssrc, offs, cnt, inv, gscale);
        gemm16<1,0,1,0><<<G1, 256, G16_SMEM_BYTES>>>(t2h, w2t, nullptr, NN, gcn_b2[L], feat, feat16,
                                                     gcn_gamma[L], gcn_beta[L], colstats,
                                                     nullptr, nullptr, nullptr, nullptr, nullptr, nullptr);

        // ---- Attention layer: seq2 fuses the key gather ----
        gemm_seq2e<<<G3, 256, SEQ_SMEM_BYTES>>>(feat16, wkaL, wvt, skah, vh, TNN,
                                                e_emb, ssrc, offs, cnt, inv);
        if (L == 0) {
            gemm_attn_out<0><<<G1, 256, G16_SMEM_BYTES>>>(feat16, wqaL, wpt, NN, at_bp[L],
                                                          feat, feat16, skah, vh, nullptr);
        } else {
            gemm_attn_out<1><<<G1, 256, G16_SMEM_BYTES>>>(feat16, wqaL, wpt, NN, at_bp[L],
                                                          feat, nullptr, skah, vh, (float*)d_out);
        }
    }

    if (out_size >= ND + TT*DD) {
        cudaMemcpyAsync((float*)d_out + ND, e_emb, TT*DD*sizeof(float),
                        cudaMemcpyDeviceToDevice, 0);
    }
}